// round 15
// baseline (speedup 1.0000x reference)
#include <cuda_runtime.h>
#include <cuda_fp16.h>
#include <cstdint>
#include <cstddef>

#define B_    256
#define P_    196
#define E_    2048
#define A_    512
#define MTOT  (B_*P_)      // 50176

#define MT 128
#define NT 128
#define KC 32
#define NKC (E_/KC)        // 64
#define NSPLIT (A_/NT)     // 4
#define NMT    (MTOT/MT)            // 392 m-tiles
#define NTILES (NMT*NSPLIT)         // 1568 gemm tiles
#define NSTAGE 6
#define TILE_B 8192
#define NPERS  296         // 2 x 148 persistent CTAs

// task schedule: 64 upfront conversions, then [4 gemm + 1 conv] groups, then tail gemm
#define LOOKAHEAD   64
#define NGROUPS     (NMT - LOOKAHEAD)            // 328
#define T_GROUP_END (LOOKAHEAD + NGROUPS*5)      // 1704
#define NTASKS      (T_GROUP_END + (NTILES - NGROUPS*4))   // 1960

// scratch
__device__ float  g_att2[B_*A_];
__device__ float  g_att [MTOT];
__device__ __half g_Bth [A_*E_];
__device__ __half g_ench[(size_t)MTOT*E_];
__device__ unsigned g_tile_ctr;
__device__ unsigned g_mflag[NMT];   // conversion-done flags

// ---------------- helpers ----------------
__device__ __forceinline__ void cp_async16(void* smem_dst, const void* gmem_src){
    unsigned s = (unsigned)__cvta_generic_to_shared(smem_dst);
    asm volatile("cp.async.cg.shared.global [%0], [%1], 16;\n" :: "r"(s), "l"(gmem_src));
}
__device__ __forceinline__ uint32_t packh(float a, float b){
    __half2 h = __floats2half2_rn(a, b);
    return *reinterpret_cast<uint32_t*>(&h);
}
__device__ __forceinline__ void mma_fp16(float c[4], const uint32_t a[4], uint32_t b0, uint32_t b1){
    asm volatile(
        "mma.sync.aligned.m16n8k16.row.col.f32.f16.f16.f32 "
        "{%0,%1,%2,%3}, {%4,%5,%6,%7}, {%8,%9}, {%0,%1,%2,%3};\n"
        : "+f"(c[0]), "+f"(c[1]), "+f"(c[2]), "+f"(c[3])
        : "r"(a[0]), "r"(a[1]), "r"(a[2]), "r"(a[3]), "r"(b0), "r"(b1));
}
__device__ __forceinline__ void ldsm_x4(uint32_t r[4], uint32_t saddr){
    asm volatile("ldmatrix.sync.aligned.m8n8.x4.shared.b16 {%0,%1,%2,%3}, [%4];"
        : "=r"(r[0]), "=r"(r[1]), "=r"(r[2]), "=r"(r[3]) : "r"(saddr));
}
__device__ __forceinline__ uint32_t smem_u32(const void* p){
    return (uint32_t)__cvta_generic_to_shared(p);
}

// ---------------- kernel 0: g_Bth[n][k] = fp16(We[k][n]) ----------------
__global__ void prep_bh(const float* __restrict__ We){
    __shared__ float t[32][33];
    const int k0 = blockIdx.x*32, n0 = blockIdx.y*32;
    const int tx = threadIdx.x, ty = threadIdx.y;   // (32,8)
    #pragma unroll
    for (int i = 0; i < 4; i++)
        t[ty + i*8][tx] = We[(size_t)(k0 + ty + i*8)*A_ + n0 + tx];
    __syncthreads();
    #pragma unroll
    for (int i = 0; i < 4; i++)
        g_Bth[(size_t)(n0 + ty + i*8)*E_ + k0 + tx] = __float2half_rn(t[tx][ty + i*8]);
}

// ---------------- kernel 1: att2/bias (64 blocks, 4 batches each) ----------------
__global__ void __launch_bounds__(256)
att2_kernel(const float* __restrict__ dh,  const float* __restrict__ Wd,
            const float* __restrict__ Wdb, const float* __restrict__ Web){
    __shared__ float dh_s[4][512];
    const int tid = threadIdx.x;
    const int bb  = blockIdx.x * 4;
    for (int i = tid; i < 4*512; i += 256)
        dh_s[i >> 9][i & 511] = dh[(size_t)bb*512 + i];
    __syncthreads();

    float acc[4][2];
    {
        const float base0 = Wdb[tid]       + Web[tid];
        const float base1 = Wdb[tid + 256] + Web[tid + 256];
        #pragma unroll
        for (int q = 0; q < 4; q++){ acc[q][0] = base0; acc[q][1] = base1; }
    }
    for (int k = 0; k < 512; k++){
        const float w0 = Wd[(size_t)k*512 + tid];
        const float w1 = Wd[(size_t)k*512 + tid + 256];
        #pragma unroll
        for (int q = 0; q < 4; q++){
            const float d = dh_s[q][k];
            acc[q][0] += d * w0;
            acc[q][1] += d * w1;
        }
    }
    #pragma unroll
    for (int q = 0; q < 4; q++){
        g_att2[(size_t)(bb+q)*512 + tid]       = acc[q][0];
        g_att2[(size_t)(bb+q)*512 + tid + 256] = acc[q][1];
    }
}

// ---------------- kernel 2: reset logits / flags / counter ----------------
__global__ void __launch_bounds__(1024)
reset_kernel(){
    const int i = blockIdx.x*1024 + threadIdx.x;    // 49 x 1024 = 50176
    if (i < MTOT) g_att[i] = 0.f;
    if (i < NMT)  g_mflag[i] = 0u;
    if (i == 0)   g_tile_ctr = 0u;
}

// ---------------- kernel 3 (ncu idx 3): persistent GEMM + inline A-conversion ----------
#define EX_OFF  (2*NSTAGE*TILE_B)                    // 98304
#define SMEM_BYTES (EX_OFF + (256 + 128 + 128 + 4)*4)

#define SWZ(row, chunk) ((row)*64 + ((((chunk) ^ (((row)>>1)&3)) & 3)*16))

#define LF(aa, bb, st, ak, bk) do {                                                 \
    ldsm_x4(aa[0], asb + (uint32_t)((st)*TILE_B) + (ak));                           \
    ldsm_x4(aa[1], asb + (uint32_t)((st)*TILE_B) + 1024 + (ak));                    \
    ldsm_x4(bb[0], bsb + (uint32_t)((st)*TILE_B) + (bk));                           \
    ldsm_x4(bb[1], bsb + (uint32_t)((st)*TILE_B) + 1024 + (bk));                    \
    ldsm_x4(bb[2], bsb + (uint32_t)((st)*TILE_B) + 2048 + (bk));                    \
    ldsm_x4(bb[3], bsb + (uint32_t)((st)*TILE_B) + 3072 + (bk));                    \
} while(0)

#define MMA_SET(aa, bb) do {                                                        \
    _Pragma("unroll")                                                               \
    for (int p = 0; p < 4; p++){                                                    \
        mma_fp16(c[0][2*p+0], aa[0], bb[p][0], bb[p][1]);                           \
        mma_fp16(c[1][2*p+0], aa[1], bb[p][0], bb[p][1]);                           \
        mma_fp16(c[0][2*p+1], aa[0], bb[p][2], bb[p][3]);                           \
        mma_fp16(c[1][2*p+1], aa[1], bb[p][2], bb[p][3]);                           \
    }                                                                               \
} while(0)

#define PREFETCH(ck, st) do {                                                       \
    const size_t ko = (size_t)(ck)*KC;                                              \
    cp_async16(smA + (size_t)((st)*TILE_B) + sw0, Agl + ko);                        \
    cp_async16(smA + (size_t)((st)*TILE_B) + sw1, Agl + ko + 8);                    \
    cp_async16(smB + (size_t)((st)*TILE_B) + sw0, Bgl + ko);                        \
    cp_async16(smB + (size_t)((st)*TILE_B) + sw1, Bgl + ko + 8);                    \
    asm volatile("cp.async.commit_group;\n");                                       \
} while(0)

#define BLK(kb, S0, S1, SP0, SP1) do {                                              \
    asm volatile("cp.async.wait_group 2;\n");                                       \
    __syncthreads();                                                                \
    LF(a0, b0, S0, aoff0, boff0);                                                   \
    PREFETCH((kb)+4, SP0);                                                          \
    LF(a1, b1, S0, aoff1, boff1);  MMA_SET(a0, b0);                                 \
    LF(a0, b0, S1, aoff0, boff0);  MMA_SET(a1, b1);                                 \
    PREFETCH((kb)+5, SP1);                                                          \
    LF(a1, b1, S1, aoff1, boff1);  MMA_SET(a0, b0);                                 \
    MMA_SET(a1, b1);                                                                \
} while(0)

#define BLK_TAIL(S0, S1, WG) do {                                                   \
    asm volatile("cp.async.wait_group " #WG ";\n");                                 \
    __syncthreads();                                                                \
    LF(a0, b0, S0, aoff0, boff0);                                                   \
    LF(a1, b1, S0, aoff1, boff1);  MMA_SET(a0, b0);                                 \
    LF(a0, b0, S1, aoff0, boff0);  MMA_SET(a1, b1);                                 \
    LF(a1, b1, S1, aoff1, boff1);  MMA_SET(a0, b0);                                 \
    MMA_SET(a1, b1);                                                                \
} while(0)

__global__ void __launch_bounds__(256, 2)
gemm_att_kernel(const float* __restrict__ enc, const float* __restrict__ Wf){
    extern __shared__ char smraw[];
    char* smA = smraw;
    char* smB = smraw + NSTAGE*TILE_B;
    float*     bias_s = (float*)(smraw + EX_OFF);
    float*     wf_s   = bias_s + 256;
    float*     satt   = wf_s + 128;
    unsigned*  s_tile = (unsigned*)(satt + 128);

    const int tid = threadIdx.x;
    const int warp = tid >> 5, lane = tid & 31;
    const int wm = warp >> 1, wn = warp & 1;
    const int g = lane >> 2, t = lane & 3;

    const int a_row = lane & 15;
    const int a_cb  = lane >> 4;
    const uint32_t aoff0 = SWZ(a_row, a_cb);
    const uint32_t aoff1 = SWZ(a_row, a_cb + 2);
    const int b_row = (lane & 7) + ((lane >> 4) & 1) * 8;
    const int b_cb  = (lane >> 3) & 1;
    const uint32_t boff0 = SWZ(b_row, b_cb);
    const uint32_t boff1 = SWZ(b_row, b_cb + 2);

    const uint32_t asb = smem_u32(smA) + (uint32_t)(wm*2048);
    const uint32_t bsb = smem_u32(smB) + (uint32_t)(wn*4096);

    const int ld_row = tid >> 1;
    const int ld_c0  = (tid & 1) * 2;
    const uint32_t sw0 = SWZ(ld_row, ld_c0);
    const uint32_t sw1 = SWZ(ld_row, ld_c0 + 1);

    for (;;){
        if (tid == 0) *s_tile = atomicAdd(&g_tile_ctr, 1u);
        __syncthreads();
        const unsigned task = *s_tile;
        if (task >= NTASKS) break;

        // ---- decode task ----
        int conv_m = -1, gt = -1;
        if (task < LOOKAHEAD){
            conv_m = (int)task;
        } else if (task < T_GROUP_END){
            const unsigned u = task - LOOKAHEAD;
            const unsigned g5 = u / 5u, r = u - g5*5u;
            if (r == 4u) conv_m = (int)(LOOKAHEAD + g5);
            else         gt = (int)(g5*4u + r);
        } else {
            gt = NGROUPS*4 + (int)(task - T_GROUP_END);
        }

        if (conv_m >= 0){
            // ---- conversion task: enc[conv_m*128 .. +128) x E -> g_ench fp16 ----
            const float* src = enc   + (size_t)conv_m * 128 * E_;
            __half*      dst = g_ench + (size_t)conv_m * 128 * E_;
            #pragma unroll 4
            for (int i = tid; i < 128*E_/8; i += 256){
                const float4 v0 = *(const float4*)(src + (size_t)i*8);
                const float4 v1 = *(const float4*)(src + (size_t)i*8 + 4);
                uint4 w;
                w.x = packh(v0.x, v0.y);  w.y = packh(v0.z, v0.w);
                w.z = packh(v1.x, v1.y);  w.w = packh(v1.z, v1.w);
                *(uint4*)(dst + (size_t)i*8) = w;
            }
            __threadfence();
            __syncthreads();
            if (tid == 0)
                asm volatile("st.release.gpu.global.u32 [%0], %1;"
                             :: "l"(&g_mflag[conv_m]), "r"(1u) : "memory");
            continue;
        }

        // ---- GEMM tile ----
        const int mi_t = gt >> 2;
        const int m0 = mi_t * MT;
        const int n0 = (gt & 3) * NT;
        const int b_first = m0 / P_;

        // wait for A-slice conversion
        if (tid == 0){
            unsigned f;
            do {
                asm volatile("ld.acquire.gpu.global.u32 %0, [%1];"
                             : "=r"(f) : "l"(&g_mflag[mi_t]) : "memory");
            } while (!f);
        }
        __syncthreads();

        const __half* Agl = g_ench + (size_t)(m0 + ld_row)*E_ + ld_c0*8;
        const __half* Bgl = g_Bth  + (size_t)(n0 + ld_row)*E_ + ld_c0*8;

        PREFETCH(0, 0);
        PREFETCH(1, 1);
        PREFETCH(2, 2);
        PREFETCH(3, 3);

        {
            int j = tid >> 7, c2 = tid & 127;
            int b = b_first + j;
            bias_s[tid] = (b < B_) ? g_att2[(size_t)b*A_ + n0 + c2] : 0.f;
            if (tid < 128){ wf_s[tid] = Wf[n0 + tid]; satt[tid] = 0.f; }
        }

        float c[2][8][4];
        #pragma unroll
        for (int mi = 0; mi < 2; mi++)
            #pragma unroll
            for (int ni = 0; ni < 8; ni++)
                #pragma unroll
                for (int j = 0; j < 4; j++) c[mi][ni][j] = 0.f;

        uint32_t a0[2][4], b0[4][4], a1[2][4], b1[4][4];

        for (int kb = 0; kb < 60; kb += 6){
            BLK(kb,   0, 1, 4, 5);
            BLK(kb+2, 2, 3, 0, 1);
            BLK(kb+4, 4, 5, 2, 3);
        }
        BLK_TAIL(0, 1, 2);
        BLK_TAIL(2, 3, 0);
        __syncthreads();

        // epilogue: h = relu(acc + bias); att += h .* Wf
        float attr[2][2] = {{0.f,0.f},{0.f,0.f}};
        #pragma unroll
        for (int ni = 0; ni < 8; ni++){
            const int cl = wn*64 + ni*8 + 2*t;
            const float w0 = wf_s[cl], w1 = wf_s[cl+1];
            #pragma unroll
            for (int mi = 0; mi < 2; mi++){
                #pragma unroll
                for (int rr = 0; rr < 2; rr++){
                    const int rowg = m0 + wm*32 + mi*16 + g + rr*8;
                    const int rb   = rowg / P_ - b_first;
                    const float bv0 = bias_s[rb*128 + cl];
                    const float bv1 = bias_s[rb*128 + cl + 1];
                    const float h0 = fmaxf(c[mi][ni][rr*2+0] + bv0, 0.f);
                    const float h1 = fmaxf(c[mi][ni][rr*2+1] + bv1, 0.f);
                    attr[mi][rr] += h0*w0 + h1*w1;
                }
            }
        }
        #pragma unroll
        for (int mi = 0; mi < 2; mi++)
            #pragma unroll
            for (int rr = 0; rr < 2; rr++){
                float v = attr[mi][rr];
                v += __shfl_xor_sync(0xffffffffu, v, 1);
                v += __shfl_xor_sync(0xffffffffu, v, 2);
                if (t == 0) atomicAdd(&satt[wm*32 + mi*16 + g + rr*8], v);
            }
        __syncthreads();
        if (tid < 128) atomicAdd(&g_att[m0 + tid], satt[tid]);
        __syncthreads();
    }
}

// ---------------- kernel 4: fused softmax + awe (one block per batch) ----------------
__global__ void __launch_bounds__(512)
awe_fused(float* __restrict__ alpha_out, float4* __restrict__ out4){
    const int b = blockIdx.x, tid = threadIdx.x;
    __shared__ float red[512];
    __shared__ float al[P_];

    float v = (tid < P_) ? g_att[b*P_ + tid] : -1e30f;
    red[tid] = v; __syncthreads();
    for (int s = 256; s > 0; s >>= 1){
        if (tid < s) red[tid] = fmaxf(red[tid], red[tid+s]);
        __syncthreads();
    }
    const float mx = red[0]; __syncthreads();
    const float e = (tid < P_) ? expf(v - mx) : 0.f;
    red[tid] = e; __syncthreads();
    for (int s = 256; s > 0; s >>= 1){
        if (tid < s) red[tid] += red[tid+s];
        __syncthreads();
    }
    const float inv = 1.f / red[0];
    if (tid < P_){
        const float a = e * inv;
        alpha_out[b*P_ + tid] = a;
        al[tid] = a;
    }
    __syncthreads();

    float4 acc = make_float4(0.f, 0.f, 0.f, 0.f);
    const uint2* ep = (const uint2*)(g_ench + (size_t)b * P_ * E_) + tid;
    #pragma unroll 4
    for (int p = 0; p < P_; p++){
        const float a = al[p];
        const uint2 u = ep[(size_t)p * (E_/4)];
        const __half2 h0 = *(const __half2*)&u.x;
        const __half2 h1 = *(const __half2*)&u.y;
        acc.x += a * __low2float(h0);  acc.y += a * __high2float(h0);
        acc.z += a * __low2float(h1);  acc.w += a * __high2float(h1);
    }
    out4[(size_t)b * (E_/4) + tid] = acc;
}

// ---------------- launch ----------------
extern "C" void kernel_launch(void* const* d_in, const int* in_sizes, int n_in,
                              void* d_out, int out_size){
    const float* enc  = (const float*)d_in[0];   // (B,P,E)
    const float* dh   = (const float*)d_in[1];   // (1,B,D)
    const float* We_w = (const float*)d_in[2];   // (E,A)
    const float* We_b = (const float*)d_in[3];   // (A)
    const float* Wd_w = (const float*)d_in[4];   // (D,A)
    const float* Wd_b = (const float*)d_in[5];   // (A)
    const float* Wf_w = (const float*)d_in[6];   // (A)
    // d_in[7] = Wf_b: scalar logit shift -> softmax-invariant, outputs don't depend on it.

    float* out       = (float*)d_out;
    float* awe_out   = out;                       // (B,E)
    float* alpha_out = out + (size_t)B_*E_;       // (B,P)

    cudaFuncSetAttribute(gemm_att_kernel, cudaFuncAttributeMaxDynamicSharedMemorySize, SMEM_BYTES);

    prep_bh       <<<dim3(E_/32, A_/32), dim3(32, 8)>>>(We_w);
    att2_kernel   <<<64, 256>>>(dh, Wd_w, Wd_b, We_b);
    reset_kernel  <<<(MTOT + 1023)/1024, 1024>>>();
    gemm_att_kernel<<<NPERS, 256, SMEM_BYTES>>>(enc, Wf_w);   // launch idx 3 -> ncu target
    awe_fused     <<<B_, 512>>>(alpha_out, (float4*)awe_out);
}

// round 16
// speedup vs baseline: 1.0840x; 1.0840x over previous
#include <cuda_runtime.h>
#include <cuda_fp16.h>
#include <cstdint>
#include <cstddef>

#define B_    256
#define P_    196
#define E_    2048
#define A_    512
#define MTOT  (B_*P_)      // 50176

#define MT 128
#define NT 128
#define KC 32
#define NKC (E_/KC)        // 64
#define NSPLIT (A_/NT)     // 4
#define NSTAGE 6
#define TILE_B 8192        // 128 rows x 64B (swizzled)

// scratch
__device__ float  g_att2[B_*A_];
__device__ float  g_att [MTOT];
__device__ __half g_Bth [A_*E_];
__device__ __half g_ench[(size_t)MTOT*E_];

// ---------------- helpers ----------------
__device__ __forceinline__ void cp_async16(void* smem_dst, const void* gmem_src){
    unsigned s = (unsigned)__cvta_generic_to_shared(smem_dst);
    asm volatile("cp.async.cg.shared.global [%0], [%1], 16;\n" :: "r"(s), "l"(gmem_src));
}
__device__ __forceinline__ uint32_t packh(float a, float b){
    __half2 h = __floats2half2_rn(a, b);
    return *reinterpret_cast<uint32_t*>(&h);
}
__device__ __forceinline__ void mma_fp16(float c[4], const uint32_t a[4], uint32_t b0, uint32_t b1){
    asm volatile(
        "mma.sync.aligned.m16n8k16.row.col.f32.f16.f16.f32 "
        "{%0,%1,%2,%3}, {%4,%5,%6,%7}, {%8,%9}, {%0,%1,%2,%3};\n"
        : "+f"(c[0]), "+f"(c[1]), "+f"(c[2]), "+f"(c[3])
        : "r"(a[0]), "r"(a[1]), "r"(a[2]), "r"(a[3]), "r"(b0), "r"(b1));
}
__device__ __forceinline__ void ldsm_x4(uint32_t r[4], uint32_t saddr){
    asm volatile("ldmatrix.sync.aligned.m8n8.x4.shared.b16 {%0,%1,%2,%3}, [%4];"
        : "=r"(r[0]), "=r"(r[1]), "=r"(r[2]), "=r"(r[3]) : "r"(saddr));
}
__device__ __forceinline__ uint32_t smem_u32(const void* p){
    return (uint32_t)__cvta_generic_to_shared(p);
}

// ---------------- kernel 0: g_Bth[n][k] = fp16(We[k][n]) ----------------
__global__ void prep_bh(const float* __restrict__ We){
    __shared__ float t[32][33];
    const int k0 = blockIdx.x*32, n0 = blockIdx.y*32;
    const int tx = threadIdx.x, ty = threadIdx.y;   // (32,8)
    #pragma unroll
    for (int i = 0; i < 4; i++)
        t[ty + i*8][tx] = We[(size_t)(k0 + ty + i*8)*A_ + n0 + tx];
    __syncthreads();
    #pragma unroll
    for (int i = 0; i < 4; i++)
        g_Bth[(size_t)(n0 + ty + i*8)*E_ + k0 + tx] = __float2half_rn(t[tx][ty + i*8]);
}

// ---------------- kernel 1: zero logits ----------------
__global__ void __launch_bounds__(1024)
reset_kernel(){
    const int i = blockIdx.x*1024 + threadIdx.x;
    if (i < MTOT) g_att[i] = 0.f;
}

// ---------------- kernel 2: att2/bias (64 blocks, 4 batches each) ----------------
__global__ void __launch_bounds__(256)
att2_kernel(const float* __restrict__ dh,  const float* __restrict__ Wd,
            const float* __restrict__ Wdb, const float* __restrict__ Web){
    __shared__ float dh_s[4][512];
    const int tid = threadIdx.x;
    const int bb  = blockIdx.x * 4;
    for (int i = tid; i < 4*512; i += 256)
        dh_s[i >> 9][i & 511] = dh[(size_t)bb*512 + i];
    __syncthreads();

    float acc[4][2];
    {
        const float base0 = Wdb[tid]       + Web[tid];
        const float base1 = Wdb[tid + 256] + Web[tid + 256];
        #pragma unroll
        for (int q = 0; q < 4; q++){ acc[q][0] = base0; acc[q][1] = base1; }
    }
    #pragma unroll 4
    for (int k = 0; k < 512; k++){
        const float w0 = Wd[(size_t)k*512 + tid];
        const float w1 = Wd[(size_t)k*512 + tid + 256];
        #pragma unroll
        for (int q = 0; q < 4; q++){
            const float d = dh_s[q][k];
            acc[q][0] += d * w0;
            acc[q][1] += d * w1;
        }
    }
    #pragma unroll
    for (int q = 0; q < 4; q++){
        g_att2[(size_t)(bb+q)*512 + tid]       = acc[q][0];
        g_att2[(size_t)(bb+q)*512 + tid + 256] = acc[q][1];
    }
}

// ---------------- kernel 3 (ncu idx 3): enc -> fp16, 16 floats/thread, MLP 4 ----------
// grid = MTOT*E/(512*16) = 12544 blocks
__global__ void __launch_bounds__(512)
prep_ench(const float* __restrict__ enc){
    const size_t i = ((size_t)blockIdx.x*512 + threadIdx.x)*16;
    const float4 v0 = *(const float4*)(enc + i);
    const float4 v1 = *(const float4*)(enc + i + 4);
    const float4 v2 = *(const float4*)(enc + i + 8);
    const float4 v3 = *(const float4*)(enc + i + 12);
    uint4 w0, w1;
    w0.x = packh(v0.x, v0.y);  w0.y = packh(v0.z, v0.w);
    w0.z = packh(v1.x, v1.y);  w0.w = packh(v1.z, v1.w);
    w1.x = packh(v2.x, v2.y);  w1.y = packh(v2.z, v2.w);
    w1.z = packh(v3.x, v3.y);  w1.w = packh(v3.z, v3.w);
    *(uint4*)(g_ench + i)     = w0;
    *(uint4*)(g_ench + i + 8) = w1;
}

// ---------------- kernel 4: fp16 GEMM, swizzled 6-stage ring (R13 config) ----------
#define EX_OFF  (2*NSTAGE*TILE_B)                    // 98304
#define SMEM_BYTES (EX_OFF + (256 + 128 + 128)*4)    // 100352

#define SWZ(row, chunk) ((row)*64 + ((((chunk) ^ (((row)>>1)&3)) & 3)*16))

#define LF(aa, bb, st, ak, bk) do {                                                 \
    ldsm_x4(aa[0], asb + (uint32_t)((st)*TILE_B) + (ak));                           \
    ldsm_x4(aa[1], asb + (uint32_t)((st)*TILE_B) + 1024 + (ak));                    \
    ldsm_x4(bb[0], bsb + (uint32_t)((st)*TILE_B) + (bk));                           \
    ldsm_x4(bb[1], bsb + (uint32_t)((st)*TILE_B) + 1024 + (bk));                    \
    ldsm_x4(bb[2], bsb + (uint32_t)((st)*TILE_B) + 2048 + (bk));                    \
    ldsm_x4(bb[3], bsb + (uint32_t)((st)*TILE_B) + 3072 + (bk));                    \
} while(0)

#define MMA_SET(aa, bb) do {                                                        \
    _Pragma("unroll")                                                               \
    for (int p = 0; p < 4; p++){                                                    \
        mma_fp16(c[0][2*p+0], aa[0], bb[p][0], bb[p][1]);                           \
        mma_fp16(c[1][2*p+0], aa[1], bb[p][0], bb[p][1]);                           \
        mma_fp16(c[0][2*p+1], aa[0], bb[p][2], bb[p][3]);                           \
        mma_fp16(c[1][2*p+1], aa[1], bb[p][2], bb[p][3]);                           \
    }                                                                               \
} while(0)

#define PREFETCH(ck, st) do {                                                       \
    const size_t ko = (size_t)(ck)*KC;                                              \
    cp_async16(smA + (size_t)((st)*TILE_B) + sw0, Agl + ko);                        \
    cp_async16(smA + (size_t)((st)*TILE_B) + sw1, Agl + ko + 8);                    \
    cp_async16(smB + (size_t)((st)*TILE_B) + sw0, Bgl + ko);                        \
    cp_async16(smB + (size_t)((st)*TILE_B) + sw1, Bgl + ko + 8);                    \
    asm volatile("cp.async.commit_group;\n");                                       \
} while(0)

#define BLK(kb, S0, S1, SP0, SP1) do {                                              \
    asm volatile("cp.async.wait_group 2;\n");                                       \
    __syncthreads();                                                                \
    LF(a0, b0, S0, aoff0, boff0);                                                   \
    PREFETCH((kb)+4, SP0);                                                          \
    LF(a1, b1, S0, aoff1, boff1);  MMA_SET(a0, b0);                                 \
    LF(a0, b0, S1, aoff0, boff0);  MMA_SET(a1, b1);                                 \
    PREFETCH((kb)+5, SP1);                                                          \
    LF(a1, b1, S1, aoff1, boff1);  MMA_SET(a0, b0);                                 \
    MMA_SET(a1, b1);                                                                \
} while(0)

#define BLK_TAIL(S0, S1, WG) do {                                                   \
    asm volatile("cp.async.wait_group " #WG ";\n");                                 \
    __syncthreads();                                                                \
    LF(a0, b0, S0, aoff0, boff0);                                                   \
    LF(a1, b1, S0, aoff1, boff1);  MMA_SET(a0, b0);                                 \
    LF(a0, b0, S1, aoff0, boff0);  MMA_SET(a1, b1);                                 \
    LF(a1, b1, S1, aoff1, boff1);  MMA_SET(a0, b0);                                 \
    MMA_SET(a1, b1);                                                                \
} while(0)

__global__ void __launch_bounds__(256, 2)
gemm_att_kernel(const float* __restrict__ Wf){
    extern __shared__ char smraw[];
    char* smA = smraw;
    char* smB = smraw + NSTAGE*TILE_B;
    float*  bias_s = (float*)(smraw + EX_OFF);            // [2][128]
    float*  wf_s   = bias_s + 256;
    float*  satt   = wf_s + 128;

    const int tid = threadIdx.x;
    const int bid = blockIdx.x;
    const int m0  = (bid >> 2) * MT;
    const int n0  = (bid & 3)  * NT;
    const int b_first = m0 / P_;

    {
        int j = tid >> 7, c2 = tid & 127;
        int b = b_first + j;
        bias_s[tid] = (b < B_) ? g_att2[(size_t)b*A_ + n0 + c2] : 0.f;
        if (tid < 128){ wf_s[tid] = Wf[n0 + tid]; satt[tid] = 0.f; }
    }

    const int warp = tid >> 5, lane = tid & 31;
    const int wm = warp >> 1, wn = warp & 1;
    const int g = lane >> 2, t = lane & 3;

    const int a_row = lane & 15;
    const int a_cb  = lane >> 4;
    const uint32_t aoff0 = SWZ(a_row, a_cb);
    const uint32_t aoff1 = SWZ(a_row, a_cb + 2);
    const int b_row = (lane & 7) + ((lane >> 4) & 1) * 8;
    const int b_cb  = (lane >> 3) & 1;
    const uint32_t boff0 = SWZ(b_row, b_cb);
    const uint32_t boff1 = SWZ(b_row, b_cb + 2);

    const uint32_t asb = smem_u32(smA) + (uint32_t)(wm*2048);
    const uint32_t bsb = smem_u32(smB) + (uint32_t)(wn*4096);

    const int ld_row = tid >> 1;
    const int ld_c0  = (tid & 1) * 2;
    const uint32_t sw0 = SWZ(ld_row, ld_c0);
    const uint32_t sw1 = SWZ(ld_row, ld_c0 + 1);
    const __half* Agl = g_ench + (size_t)(m0 + ld_row)*E_ + ld_c0*8;
    const __half* Bgl = g_Bth  + (size_t)(n0 + ld_row)*E_ + ld_c0*8;

    float c[2][8][4];
    #pragma unroll
    for (int mi = 0; mi < 2; mi++)
        #pragma unroll
        for (int ni = 0; ni < 8; ni++)
            #pragma unroll
            for (int j = 0; j < 4; j++) c[mi][ni][j] = 0.f;

    uint32_t a0[2][4], b0[4][4], a1[2][4], b1[4][4];

    PREFETCH(0, 0);
    PREFETCH(1, 1);
    PREFETCH(2, 2);
    PREFETCH(3, 3);

    for (int kb = 0; kb < 60; kb += 6){
        BLK(kb,   0, 1, 4, 5);
        BLK(kb+2, 2, 3, 0, 1);
        BLK(kb+4, 4, 5, 2, 3);
    }
    BLK_TAIL(0, 1, 2);
    BLK_TAIL(2, 3, 0);
    __syncthreads();

    // epilogue: h = relu(acc + bias); att += h .* Wf
    float attr[2][2] = {{0.f,0.f},{0.f,0.f}};
    #pragma unroll
    for (int ni = 0; ni < 8; ni++){
        const int cl = wn*64 + ni*8 + 2*t;
        const float w0 = wf_s[cl], w1 = wf_s[cl+1];
        #pragma unroll
        for (int mi = 0; mi < 2; mi++){
            #pragma unroll
            for (int rr = 0; rr < 2; rr++){
                const int rowg = m0 + wm*32 + mi*16 + g + rr*8;
                const int rb   = rowg / P_ - b_first;
                const float bv0 = bias_s[rb*128 + cl];
                const float bv1 = bias_s[rb*128 + cl + 1];
                const float h0 = fmaxf(c[mi][ni][rr*2+0] + bv0, 0.f);
                const float h1 = fmaxf(c[mi][ni][rr*2+1] + bv1, 0.f);
                attr[mi][rr] += h0*w0 + h1*w1;
            }
        }
    }
    #pragma unroll
    for (int mi = 0; mi < 2; mi++)
        #pragma unroll
        for (int rr = 0; rr < 2; rr++){
            float v = attr[mi][rr];
            v += __shfl_xor_sync(0xffffffffu, v, 1);
            v += __shfl_xor_sync(0xffffffffu, v, 2);
            if (t == 0) atomicAdd(&satt[wm*32 + mi*16 + g + rr*8], v);
        }
    __syncthreads();
    if (tid < 128) atomicAdd(&g_att[m0 + tid], satt[tid]);
}

// ---------------- kernel 5: fused softmax + awe (one block per batch) ----------------
__global__ void __launch_bounds__(512)
awe_fused(float* __restrict__ alpha_out, float4* __restrict__ out4){
    const int b = blockIdx.x, tid = threadIdx.x;
    __shared__ float red[512];
    __shared__ float al[P_];

    float v = (tid < P_) ? g_att[b*P_ + tid] : -1e30f;
    red[tid] = v; __syncthreads();
    for (int s = 256; s > 0; s >>= 1){
        if (tid < s) red[tid] = fmaxf(red[tid], red[tid+s]);
        __syncthreads();
    }
    const float mx = red[0]; __syncthreads();
    const float e = (tid < P_) ? expf(v - mx) : 0.f;
    red[tid] = e; __syncthreads();
    for (int s = 256; s > 0; s >>= 1){
        if (tid < s) red[tid] += red[tid+s];
        __syncthreads();
    }
    const float inv = 1.f / red[0];
    if (tid < P_){
        const float a = e * inv;
        alpha_out[b*P_ + tid] = a;
        al[tid] = a;
    }
    __syncthreads();

    float4 acc = make_float4(0.f, 0.f, 0.f, 0.f);
    const uint2* ep = (const uint2*)(g_ench + (size_t)b * P_ * E_) + tid;
    #pragma unroll 4
    for (int p = 0; p < P_; p++){
        const float a = al[p];
        const uint2 u = ep[(size_t)p * (E_/4)];
        const __half2 h0 = *(const __half2*)&u.x;
        const __half2 h1 = *(const __half2*)&u.y;
        acc.x += a * __low2float(h0);  acc.y += a * __high2float(h0);
        acc.z += a * __low2float(h1);  acc.w += a * __high2float(h1);
    }
    out4[(size_t)b * (E_/4) + tid] = acc;
}

// ---------------- launch ----------------
extern "C" void kernel_launch(void* const* d_in, const int* in_sizes, int n_in,
                              void* d_out, int out_size){
    const float* enc  = (const float*)d_in[0];   // (B,P,E)
    const float* dh   = (const float*)d_in[1];   // (1,B,D)
    const float* We_w = (const float*)d_in[2];   // (E,A)
    const float* We_b = (const float*)d_in[3];   // (A)
    const float* Wd_w = (const float*)d_in[4];   // (D,A)
    const float* Wd_b = (const float*)d_in[5];   // (A)
    const float* Wf_w = (const float*)d_in[6];   // (A)
    // d_in[7] = Wf_b: scalar logit shift -> softmax-invariant, outputs don't depend on it.

    float* out       = (float*)d_out;
    float* awe_out   = out;                       // (B,E)
    float* alpha_out = out + (size_t)B_*E_;       // (B,P)

    cudaFuncSetAttribute(gemm_att_kernel, cudaFuncAttributeMaxDynamicSharedMemorySize, SMEM_BYTES);

    prep_bh       <<<dim3(E_/32, A_/32), dim3(32, 8)>>>(We_w);       // idx 0
    reset_kernel  <<<(MTOT + 1023)/1024, 1024>>>();                  // idx 1
    att2_kernel   <<<64, 256>>>(dh, Wd_w, Wd_b, We_b);               // idx 2
    prep_ench     <<<(int)((size_t)MTOT*E_/(512*16)), 512>>>(enc);   // idx 3 -> ncu target
    gemm_att_kernel<<<(MTOT/MT)*NSPLIT, 256, SMEM_BYTES>>>(Wf_w);    // idx 4
    awe_fused     <<<B_, 512>>>(alpha_out, (float4*)awe_out);        // idx 5
}

// round 17
// speedup vs baseline: 1.2595x; 1.1618x over previous
#include <cuda_runtime.h>
#include <cuda_fp16.h>
#include <cstdint>
#include <cstddef>

#define B_    256
#define P_    196
#define E_    2048
#define A_    512
#define MTOT  (B_*P_)      // 50176

#define MT 128
#define NT 128
#define KC 32
#define NKC (E_/KC)        // 64
#define NSPLIT (A_/NT)     // 4
#define NSTAGE 6
#define TILE_B 8192        // 128 rows x 64B (swizzled)

// combo grid layout
#define NB_ATT2 32
#define NB_BH   512
#define NB_ENCH ((int)((size_t)MTOT*E_/(512*16)))   // 12544
#define NB_COMBO (NB_ATT2 + NB_BH + NB_ENCH)        // 13088

// scratch
__device__ float  g_att2[B_*A_];
__device__ float  g_att [MTOT];
__device__ __half g_Bth [A_*E_];
__device__ __half g_ench[(size_t)MTOT*E_];

// ---------------- helpers ----------------
__device__ __forceinline__ void cp_async16(void* smem_dst, const void* gmem_src){
    unsigned s = (unsigned)__cvta_generic_to_shared(smem_dst);
    asm volatile("cp.async.cg.shared.global [%0], [%1], 16;\n" :: "r"(s), "l"(gmem_src));
}
__device__ __forceinline__ uint32_t packh(float a, float b){
    __half2 h = __floats2half2_rn(a, b);
    return *reinterpret_cast<uint32_t*>(&h);
}
__device__ __forceinline__ void mma_fp16(float c[4], const uint32_t a[4], uint32_t b0, uint32_t b1){
    asm volatile(
        "mma.sync.aligned.m16n8k16.row.col.f32.f16.f16.f32 "
        "{%0,%1,%2,%3}, {%4,%5,%6,%7}, {%8,%9}, {%0,%1,%2,%3};\n"
        : "+f"(c[0]), "+f"(c[1]), "+f"(c[2]), "+f"(c[3])
        : "r"(a[0]), "r"(a[1]), "r"(a[2]), "r"(a[3]), "r"(b0), "r"(b1));
}
__device__ __forceinline__ void ldsm_x4(uint32_t r[4], uint32_t saddr){
    asm volatile("ldmatrix.sync.aligned.m8n8.x4.shared.b16 {%0,%1,%2,%3}, [%4];"
        : "=r"(r[0]), "=r"(r[1]), "=r"(r[2]), "=r"(r[3]) : "r"(saddr));
}
__device__ __forceinline__ uint32_t smem_u32(const void* p){
    return (uint32_t)__cvta_generic_to_shared(p);
}

// ---------------- kernel 0: fused front-end ----------------
// bid [0,32): att2 (8 batches/block) | [32,544): Bth transpose (2 tiles/block)
// | [544, 13088): enc->fp16 (16 floats/thread) + zero g_att
__global__ void __launch_bounds__(512)
combo_kernel(const float* __restrict__ enc, const float* __restrict__ dh,
             const float* __restrict__ We,  const float* __restrict__ Wd,
             const float* __restrict__ Wdb, const float* __restrict__ Web){
    __shared__ float sm[8*512];                       // 16KB, reused by all roles
    const int bid = blockIdx.x;
    const int tid = threadIdx.x;

    if (bid >= NB_ATT2 + NB_BH){
        // ---- enc -> fp16 + zero logits ----
        const int eb = bid - (NB_ATT2 + NB_BH);
        const size_t i = ((size_t)eb*512 + tid)*16;
        const float4 v0 = *(const float4*)(enc + i);
        const float4 v1 = *(const float4*)(enc + i + 4);
        const float4 v2 = *(const float4*)(enc + i + 8);
        const float4 v3 = *(const float4*)(enc + i + 12);
        uint4 w0, w1;
        w0.x = packh(v0.x, v0.y);  w0.y = packh(v0.z, v0.w);
        w0.z = packh(v1.x, v1.y);  w0.w = packh(v1.z, v1.w);
        w1.x = packh(v2.x, v2.y);  w1.y = packh(v2.z, v2.w);
        w1.z = packh(v3.x, v3.y);  w1.w = packh(v3.z, v3.w);
        *(uint4*)(g_ench + i)     = w0;
        *(uint4*)(g_ench + i + 8) = w1;
        const int j = eb*512 + tid;
        if (j < MTOT) g_att[j] = 0.f;
        return;
    }

    if (bid < NB_ATT2){
        // ---- att2: bias = dh@Wd + Wd_b + We_b, 8 batch rows per block ----
        float (*dh_s)[512] = (float(*)[512])sm;
        const int bb = bid * 8;
        for (int i = tid; i < 8*512; i += 512)
            dh_s[i >> 9][i & 511] = dh[(size_t)bb*512 + i];
        __syncthreads();

        float acc[8];
        const float base = Wdb[tid] + Web[tid];
        #pragma unroll
        for (int q = 0; q < 8; q++) acc[q] = base;
        #pragma unroll 4
        for (int k = 0; k < 512; k++){
            const float w = Wd[(size_t)k*512 + tid];
            #pragma unroll
            for (int q = 0; q < 8; q++) acc[q] += dh_s[q][k] * w;
        }
        #pragma unroll
        for (int q = 0; q < 8; q++)
            g_att2[(size_t)(bb+q)*512 + tid] = acc[q];
        return;
    }

    // ---- Bth transpose: 2 (32x32) tiles per block ----
    {
        float (*t)[32][33] = (float(*)[32][33])sm;
        const int half = tid >> 8;                    // 0/1
        const int t256 = tid & 255;
        const int tx = t256 & 31, ty = t256 >> 5;     // (32,8)
        const int tt = (bid - NB_ATT2)*2 + half;      // tile id in [0,1024)
        const int k0 = (tt & 63) * 32;
        const int n0 = (tt >> 6) * 32;
        #pragma unroll
        for (int i = 0; i < 4; i++)
            t[half][ty + i*8][tx] = We[(size_t)(k0 + ty + i*8)*A_ + n0 + tx];
        __syncthreads();
        #pragma unroll
        for (int i = 0; i < 4; i++)
            g_Bth[(size_t)(n0 + ty + i*8)*E_ + k0 + tx] = __float2half_rn(t[half][tx][ty + i*8]);
        return;
    }
}

// ---------------- kernel 1: fp16 GEMM, swizzled 6-stage ring (R13 config) ----------
#define EX_OFF  (2*NSTAGE*TILE_B)                    // 98304
#define SMEM_BYTES (EX_OFF + (256 + 128 + 128)*4)    // 100352

#define SWZ(row, chunk) ((row)*64 + ((((chunk) ^ (((row)>>1)&3)) & 3)*16))

#define LF(aa, bb, st, ak, bk) do {                                                 \
    ldsm_x4(aa[0], asb + (uint32_t)((st)*TILE_B) + (ak));                           \
    ldsm_x4(aa[1], asb + (uint32_t)((st)*TILE_B) + 1024 + (ak));                    \
    ldsm_x4(bb[0], bsb + (uint32_t)((st)*TILE_B) + (bk));                           \
    ldsm_x4(bb[1], bsb + (uint32_t)((st)*TILE_B) + 1024 + (bk));                    \
    ldsm_x4(bb[2], bsb + (uint32_t)((st)*TILE_B) + 2048 + (bk));                    \
    ldsm_x4(bb[3], bsb + (uint32_t)((st)*TILE_B) + 3072 + (bk));                    \
} while(0)

#define MMA_SET(aa, bb) do {                                                        \
    _Pragma("unroll")                                                               \
    for (int p = 0; p < 4; p++){                                                    \
        mma_fp16(c[0][2*p+0], aa[0], bb[p][0], bb[p][1]);                           \
        mma_fp16(c[1][2*p+0], aa[1], bb[p][0], bb[p][1]);                           \
        mma_fp16(c[0][2*p+1], aa[0], bb[p][2], bb[p][3]);                           \
        mma_fp16(c[1][2*p+1], aa[1], bb[p][2], bb[p][3]);                           \
    }                                                                               \
} while(0)

#define PREFETCH(ck, st) do {                                                       \
    const size_t ko = (size_t)(ck)*KC;                                              \
    cp_async16(smA + (size_t)((st)*TILE_B) + sw0, Agl + ko);                        \
    cp_async16(smA + (size_t)((st)*TILE_B) + sw1, Agl + ko + 8);                    \
    cp_async16(smB + (size_t)((st)*TILE_B) + sw0, Bgl + ko);                        \
    cp_async16(smB + (size_t)((st)*TILE_B) + sw1, Bgl + ko + 8);                    \
    asm volatile("cp.async.commit_group;\n");                                       \
} while(0)

#define BLK(kb, S0, S1, SP0, SP1) do {                                              \
    asm volatile("cp.async.wait_group 2;\n");                                       \
    __syncthreads();                                                                \
    LF(a0, b0, S0, aoff0, boff0);                                                   \
    PREFETCH((kb)+4, SP0);                                                          \
    LF(a1, b1, S0, aoff1, boff1);  MMA_SET(a0, b0);                                 \
    LF(a0, b0, S1, aoff0, boff0);  MMA_SET(a1, b1);                                 \
    PREFETCH((kb)+5, SP1);                                                          \
    LF(a1, b1, S1, aoff1, boff1);  MMA_SET(a0, b0);                                 \
    MMA_SET(a1, b1);                                                                \
} while(0)

#define BLK_TAIL(S0, S1, WG) do {                                                   \
    asm volatile("cp.async.wait_group " #WG ";\n");                                 \
    __syncthreads();                                                                \
    LF(a0, b0, S0, aoff0, boff0);                                                   \
    LF(a1, b1, S0, aoff1, boff1);  MMA_SET(a0, b0);                                 \
    LF(a0, b0, S1, aoff0, boff0);  MMA_SET(a1, b1);                                 \
    LF(a1, b1, S1, aoff1, boff1);  MMA_SET(a0, b0);                                 \
    MMA_SET(a1, b1);                                                                \
} while(0)

__global__ void __launch_bounds__(256, 2)
gemm_att_kernel(const float* __restrict__ Wf){
    extern __shared__ char smraw[];
    char* smA = smraw;
    char* smB = smraw + NSTAGE*TILE_B;
    float*  bias_s = (float*)(smraw + EX_OFF);            // [2][128]
    float*  wf_s   = bias_s + 256;
    float*  satt   = wf_s + 128;

    const int tid = threadIdx.x;
    const int bid = blockIdx.x;
    const int m0  = (bid >> 2) * MT;
    const int n0  = (bid & 3)  * NT;
    const int b_first = m0 / P_;

    {
        int j = tid >> 7, c2 = tid & 127;
        int b = b_first + j;
        bias_s[tid] = (b < B_) ? g_att2[(size_t)b*A_ + n0 + c2] : 0.f;
        if (tid < 128){ wf_s[tid] = Wf[n0 + tid]; satt[tid] = 0.f; }
    }

    const int warp = tid >> 5, lane = tid & 31;
    const int wm = warp >> 1, wn = warp & 1;
    const int g = lane >> 2, t = lane & 3;

    const int a_row = lane & 15;
    const int a_cb  = lane >> 4;
    const uint32_t aoff0 = SWZ(a_row, a_cb);
    const uint32_t aoff1 = SWZ(a_row, a_cb + 2);
    const int b_row = (lane & 7) + ((lane >> 4) & 1) * 8;
    const int b_cb  = (lane >> 3) & 1;
    const uint32_t boff0 = SWZ(b_row, b_cb);
    const uint32_t boff1 = SWZ(b_row, b_cb + 2);

    const uint32_t asb = smem_u32(smA) + (uint32_t)(wm*2048);
    const uint32_t bsb = smem_u32(smB) + (uint32_t)(wn*4096);

    const int ld_row = tid >> 1;
    const int ld_c0  = (tid & 1) * 2;
    const uint32_t sw0 = SWZ(ld_row, ld_c0);
    const uint32_t sw1 = SWZ(ld_row, ld_c0 + 1);
    const __half* Agl = g_ench + (size_t)(m0 + ld_row)*E_ + ld_c0*8;
    const __half* Bgl = g_Bth  + (size_t)(n0 + ld_row)*E_ + ld_c0*8;

    float c[2][8][4];
    #pragma unroll
    for (int mi = 0; mi < 2; mi++)
        #pragma unroll
        for (int ni = 0; ni < 8; ni++)
            #pragma unroll
            for (int j = 0; j < 4; j++) c[mi][ni][j] = 0.f;

    uint32_t a0[2][4], b0[4][4], a1[2][4], b1[4][4];

    PREFETCH(0, 0);
    PREFETCH(1, 1);
    PREFETCH(2, 2);
    PREFETCH(3, 3);

    for (int kb = 0; kb < 60; kb += 6){
        BLK(kb,   0, 1, 4, 5);
        BLK(kb+2, 2, 3, 0, 1);
        BLK(kb+4, 4, 5, 2, 3);
    }
    BLK_TAIL(0, 1, 2);
    BLK_TAIL(2, 3, 0);
    __syncthreads();

    // epilogue: h = relu(acc + bias); att += h .* Wf
    float attr[2][2] = {{0.f,0.f},{0.f,0.f}};
    #pragma unroll
    for (int ni = 0; ni < 8; ni++){
        const int cl = wn*64 + ni*8 + 2*t;
        const float w0 = wf_s[cl], w1 = wf_s[cl+1];
        #pragma unroll
        for (int mi = 0; mi < 2; mi++){
            #pragma unroll
            for (int rr = 0; rr < 2; rr++){
                const int rowg = m0 + wm*32 + mi*16 + g + rr*8;
                const int rb   = rowg / P_ - b_first;
                const float bv0 = bias_s[rb*128 + cl];
                const float bv1 = bias_s[rb*128 + cl + 1];
                const float h0 = fmaxf(c[mi][ni][rr*2+0] + bv0, 0.f);
                const float h1 = fmaxf(c[mi][ni][rr*2+1] + bv1, 0.f);
                attr[mi][rr] += h0*w0 + h1*w1;
            }
        }
    }
    #pragma unroll
    for (int mi = 0; mi < 2; mi++)
        #pragma unroll
        for (int rr = 0; rr < 2; rr++){
            float v = attr[mi][rr];
            v += __shfl_xor_sync(0xffffffffu, v, 1);
            v += __shfl_xor_sync(0xffffffffu, v, 2);
            if (t == 0) atomicAdd(&satt[wm*32 + mi*16 + g + rr*8], v);
        }
    __syncthreads();
    if (tid < 128) atomicAdd(&g_att[m0 + tid], satt[tid]);
}

// ---------------- kernel 2: softmax over P per batch row ----------------
__global__ void softmax_kernel(float* __restrict__ alpha_out){
    const int b = blockIdx.x, tid = threadIdx.x;    // 256 threads
    __shared__ float red[256];
    float v = (tid < P_) ? g_att[b*P_ + tid] : -1e30f;
    red[tid] = v; __syncthreads();
    for (int s = 128; s > 0; s >>= 1){
        if (tid < s) red[tid] = fmaxf(red[tid], red[tid+s]);
        __syncthreads();
    }
    const float mx = red[0]; __syncthreads();
    const float e = (tid < P_) ? expf(v - mx) : 0.f;
    red[tid] = e; __syncthreads();
    for (int s = 128; s > 0; s >>= 1){
        if (tid < s) red[tid] += red[tid+s];
        __syncthreads();
    }
    const float inv = 1.f / red[0];
    if (tid < P_) alpha_out[b*P_ + tid] = e * inv;
}

// ---------------- kernel 3 (ncu idx 3): awe, split over 2 E-halves ----------------
// grid 512: b = bid>>1, eh = bid&1. 256 threads, uint2 (4 halves) each.
__global__ void __launch_bounds__(256)
awe_kernel(const float* __restrict__ alpha, float4* __restrict__ out4){
    const int bid = blockIdx.x, tid = threadIdx.x;
    const int b = bid >> 1, eh = bid & 1;
    __shared__ float al[P_];
    if (tid < P_) al[tid] = alpha[b*P_ + tid];
    __syncthreads();
    float4 acc = make_float4(0.f, 0.f, 0.f, 0.f);
    const uint2* ep = (const uint2*)(g_ench + (size_t)b * P_ * E_ + eh*(E_/2)) + tid;
    #pragma unroll 4
    for (int p = 0; p < P_; p++){
        const float a = al[p];
        const uint2 u = ep[(size_t)p * (E_/4)];
        const __half2 h0 = *(const __half2*)&u.x;
        const __half2 h1 = *(const __half2*)&u.y;
        acc.x += a * __low2float(h0);  acc.y += a * __high2float(h0);
        acc.z += a * __low2float(h1);  acc.w += a * __high2float(h1);
    }
    out4[(size_t)b * (E_/4) + eh*(E_/8) + tid] = acc;
}

// ---------------- launch ----------------
extern "C" void kernel_launch(void* const* d_in, const int* in_sizes, int n_in,
                              void* d_out, int out_size){
    const float* enc  = (const float*)d_in[0];   // (B,P,E)
    const float* dh   = (const float*)d_in[1];   // (1,B,D)
    const float* We_w = (const float*)d_in[2];   // (E,A)
    const float* We_b = (const float*)d_in[3];   // (A)
    const float* Wd_w = (const float*)d_in[4];   // (D,A)
    const float* Wd_b = (const float*)d_in[5];   // (A)
    const float* Wf_w = (const float*)d_in[6];   // (A)
    // d_in[7] = Wf_b: scalar logit shift -> softmax-invariant, outputs don't depend on it.

    float* out       = (float*)d_out;
    float* awe_out   = out;                       // (B,E)
    float* alpha_out = out + (size_t)B_*E_;       // (B,P)

    cudaFuncSetAttribute(gemm_att_kernel, cudaFuncAttributeMaxDynamicSharedMemorySize, SMEM_BYTES);

    combo_kernel  <<<NB_COMBO, 512>>>(enc, dh, We_w, Wd_w, Wd_b, We_b);   // idx 0
    gemm_att_kernel<<<(MTOT/MT)*NSPLIT, 256, SMEM_BYTES>>>(Wf_w);         // idx 1
    softmax_kernel<<<B_, 256>>>(alpha_out);                               // idx 2
    awe_kernel    <<<B_*2, 256>>>(alpha_out, (float4*)awe_out);           // idx 3 -> ncu
}